// round 4
// baseline (speedup 1.0000x reference)
#include <cuda_runtime.h>
#include <cuda_bf16.h>

// MPS contraction: pairs -> batch-independent quad-combos (R, fp32) ->
// per-batch quad matrices (Q, bf16, via packed f32x2 FMA) ->
// register-resident boundary-vector chains (fp32 accum, bf16 operands).
// N=1024 sites, B=256, D=16, d=2, C=10.

#define NPAIR 512
#define NQUAD 256          // quads 0..127 left, 128..255 right (stored transposed)
#define B_DIM 256
#define C_DIM 10

// g_M[p][k*16+j] = float4(M00,M01,M10,M11)[k][j]; transposed storage for p>=256.
__device__ float4 g_M[NPAIR * 256];            // 2 MB
// g_C[p*256+b] = (x0y0, x0y1, x1y0, x1y1)
__device__ float4 g_C[NPAIR * B_DIM];          // 2 MB
// g_R[q*4096 + g*256 + j*16 + k] : combo g = e*4+f, COLUMN-major-per-(g): k contiguous
__device__ float g_R[NQUAD * 16 * 256];        // 4 MB
// g_Qh: bf16, index b*65536 + q*256 + j*16 + k   (column j of quad q, k contiguous)
__device__ __nv_bfloat16 g_Qh[(size_t)B_DIM * NQUAD * 256]; // 32 MB

// ---- packed f32x2 helpers --------------------------------------------------
__device__ __forceinline__ unsigned long long pack2(float lo, float hi) {
    unsigned long long r;
    asm("mov.b64 %0, {%1, %2};" : "=l"(r) : "f"(lo), "f"(hi));
    return r;
}
__device__ __forceinline__ void fma2(unsigned long long& d,
                                     unsigned long long a, unsigned long long b) {
    asm("fma.rn.f32x2 %0, %1, %2, %0;" : "+l"(d) : "l"(a), "l"(b));
}
// pack f32x2 (lo=k even, hi=k odd) -> bf16x2 word (low half = lo)
__device__ __forceinline__ unsigned cvt_bf16x2(unsigned long long v) {
    float lo, hi; unsigned p;
    asm("mov.b64 {%0, %1}, %2;" : "=f"(lo), "=f"(hi) : "l"(v));
    asm("cvt.rn.satfinite.bf16x2.f32 %0, %1, %2;" : "=r"(p) : "f"(hi), "f"(lo));
    return p;
}

// ---------------------------------------------------------------------------
// K1: pair matrices (batch-independent) + coefficients. grid=512, block=256.
// ---------------------------------------------------------------------------
__global__ __launch_bounds__(256)
void pair_kernel(const float* __restrict__ tensor, const float* __restrict__ x)
{
    __shared__ float T0[512], T1[512];   // [l][r][dd]
    const int p = blockIdx.x;
    const int t = threadIdx.x;

    const float* base = tensor + (size_t)p * 1024;
    T0[t]       = base[t];
    T0[t + 256] = base[t + 256];
    T1[t]       = base[512 + t];
    T1[t + 256] = base[768 + t];
    __syncthreads();

    const int l = t >> 4;
    const int r = t & 15;
    float a00 = 0.f, a01 = 0.f, a10 = 0.f, a11 = 0.f;
#pragma unroll
    for (int k = 0; k < 16; k++) {
        const float2 a = *(const float2*)&T0[l * 32 + k * 2];
        const float2 b = *(const float2*)&T1[k * 32 + r * 2];
        a00 = fmaf(a.x, b.x, a00);
        a01 = fmaf(a.x, b.y, a01);
        a10 = fmaf(a.y, b.x, a10);
        a11 = fmaf(a.y, b.y, a11);
    }
    const int idx = (p < 256) ? (l * 16 + r) : (r * 16 + l);   // transpose right side
    g_M[p * 256 + idx] = make_float4(a00, a01, a10, a11);

    const float2 xa = *(const float2*)&x[(size_t)(2 * p) * 512 + t * 2];
    const float2 xb = *(const float2*)&x[(size_t)(2 * p) * 512 + 512 + t * 2];
    g_C[p * 256 + t] = make_float4(xa.x * xb.x, xa.x * xb.y, xa.y * xb.x, xa.y * xb.y);
}

// ---------------------------------------------------------------------------
// K2: R_g[q] for all 16 combos, stored k-contiguous per column.
// grid=256 (one per quad), block=256 = (16 combos x 16 columns).
// Left (q<128):  R_g = S_{2q,e} @ S_{2q+1,f}
// Right(q>=128): R_g = S_{2q+1,f} @ S_{2q,e}   (transposed quad)
// Thread (g, jj) computes column jj: acc[k] = sum_m P1[k][m] * P2[m][jj].
// ---------------------------------------------------------------------------
__global__ __launch_bounds__(256)
void r_kernel()
{
    __shared__ float SA[4][16 * 17], SB[4][16 * 17];
    const int q = blockIdx.x;
    const int t = threadIdx.x;

    {
        const float4 fa = g_M[(2 * q) * 256 + t];
        const float4 fb = g_M[(2 * q + 1) * 256 + t];
        const int k = t >> 4, j = t & 15;
        SA[0][k * 17 + j] = fa.x; SA[1][k * 17 + j] = fa.y;
        SA[2][k * 17 + j] = fa.z; SA[3][k * 17 + j] = fa.w;
        SB[0][k * 17 + j] = fb.x; SB[1][k * 17 + j] = fb.y;
        SB[2][k * 17 + j] = fb.z; SB[3][k * 17 + j] = fb.w;
    }
    __syncthreads();

    const int g  = t >> 4;     // combo e*4+f
    const int jj = t & 15;     // output column
    const int e = g >> 2, f = g & 3;
    const float* P1 = (q < 128) ? SA[e] : SB[f];
    const float* P2 = (q < 128) ? SB[f] : SA[e];

    float acc[16];
#pragma unroll
    for (int k = 0; k < 16; k++) acc[k] = 0.f;
#pragma unroll
    for (int m = 0; m < 16; m++) {
        const float bsc = P2[m * 17 + jj];
#pragma unroll
        for (int k = 0; k < 16; k++)
            acc[k] = fmaf(P1[k * 17 + m], bsc, acc[k]);
    }
    float4* dst = (float4*)&g_R[q * 4096 + g * 256 + jj * 16];
    dst[0] = make_float4(acc[0],  acc[1],  acc[2],  acc[3]);
    dst[1] = make_float4(acc[4],  acc[5],  acc[6],  acc[7]);
    dst[2] = make_float4(acc[8],  acc[9],  acc[10], acc[11]);
    dst[3] = make_float4(acc[12], acc[13], acc[14], acc[15]);
}

// ---------------------------------------------------------------------------
// K3: per-batch quad matrices, packed f32x2. Qd[b][q] = sum_g (cA_e cB_f) R_g.
// grid = (8 batch-slices, 256 quads), block = 256 = (16 bgroups x 16 cols).
// Thread (bg, j): 2 batches, column j as 8 packed k-pairs. Output bf16.
// ---------------------------------------------------------------------------
__global__ __launch_bounds__(256)
void q_kernel()
{
    __shared__ float Rsh[4096];    // 16 KB, same layout as g_R slice
    const int q = blockIdx.y;
    const int t = threadIdx.x;

    {   // stage R for this quad (coalesced, layout-agnostic copy)
        const float4* src = (const float4*)&g_R[q * 4096 + t * 16];
        float4* dst = (float4*)&Rsh[t * 16];
        dst[0] = src[0]; dst[1] = src[1]; dst[2] = src[2]; dst[3] = src[3];
    }
    __syncthreads();

    const int bg = t >> 4;
    const int j  = t & 15;
    const int b0 = blockIdx.x * 32 + bg * 2;

    float cA[2][4], cB[2][4];
#pragma unroll
    for (int bb = 0; bb < 2; bb++) {
        const float4 a = g_C[(2 * q) * 256 + b0 + bb];
        const float4 c = g_C[(2 * q + 1) * 256 + b0 + bb];
        cA[bb][0] = a.x; cA[bb][1] = a.y; cA[bb][2] = a.z; cA[bb][3] = a.w;
        cB[bb][0] = c.x; cB[bb][1] = c.y; cB[bb][2] = c.z; cB[bb][3] = c.w;
    }

    unsigned long long acc[2][8];
#pragma unroll
    for (int bb = 0; bb < 2; bb++)
#pragma unroll
        for (int kp = 0; kp < 8; kp++) acc[bb][kp] = 0ull;

#pragma unroll
    for (int e = 0; e < 4; e++) {
#pragma unroll
        for (int f = 0; f < 4; f++) {
            const float c0s = cA[0][e] * cB[0][f];
            const float c1s = cA[1][e] * cB[1][f];
            const unsigned long long c0 = pack2(c0s, c0s);
            const unsigned long long c1 = pack2(c1s, c1s);
            const unsigned long long* Rp =
                (const unsigned long long*)&Rsh[(e * 4 + f) * 256 + j * 16];
#pragma unroll
            for (int kp = 0; kp < 8; kp++) {
                const unsigned long long r = Rp[kp];
                fma2(acc[0][kp], c0, r);
                fma2(acc[1][kp], c1, r);
            }
        }
    }

#pragma unroll
    for (int bb = 0; bb < 2; bb++) {
        unsigned w[8];
#pragma unroll
        for (int kp = 0; kp < 8; kp++) w[kp] = cvt_bf16x2(acc[bb][kp]);
        // 32 contiguous bytes at (b, q, j, k=0..15)
        uint4* dst = (uint4*)(g_Qh + (size_t)(b0 + bb) * 65536 + q * 256 + j * 16);
        dst[0] = make_uint4(w[0], w[1], w[2], w[3]);
        dst[1] = make_uint4(w[4], w[5], w[6], w[7]);
    }
}

// ---------------------------------------------------------------------------
// K4: chains, register-resident, bf16 operands, prefetch depth 4, no sync.
// grid=256 one-warp blocks. Block = one batch; lanes 0-15 left chain,
// lanes 16-31 right chain (transposed quads, descending q).
// ---------------------------------------------------------------------------
__global__ __launch_bounds__(32)
void chain_kernel(const float* __restrict__ Aout, float* __restrict__ out)
{
    const int b    = blockIdx.x;
    const int lane = threadIdx.x;
    const int h    = lane >> 4;
    const int j    = lane & 15;

    // column base: bf16 index b*65536 + q*256 + j*16 + k ; uint4 = 8 bf16
    const uint4* base = (const uint4*)(g_Qh + (size_t)b * 65536 + j * 16);
    // step q: base[q*32 + 0], base[q*32 + 1]

    uint4 buf[4][2];
#pragma unroll
    for (int d = 0; d < 4; d++) {
        const int q = h ? (255 - d) : d;
        buf[d][0] = base[q * 32 + 0];
        buf[d][1] = base[q * 32 + 1];
    }

    float v[16];
#pragma unroll
    for (int k = 0; k < 16; k++) v[k] = (k == 0) ? 1.f : 0.f;
    float vp = 0.f;

    for (int t = 0; t < 128; t++) {
        uint4* cur = buf[t & 3];

        // decode 16 bf16 -> fp32 (shift/mask, alu pipe)
        float col[16];
        {
            const unsigned u[4] = {cur[0].x, cur[0].y, cur[0].z, cur[0].w};
            const unsigned w[4] = {cur[1].x, cur[1].y, cur[1].z, cur[1].w};
#pragma unroll
            for (int c = 0; c < 4; c++) {
                col[2 * c]     = __uint_as_float(u[c] << 16);
                col[2 * c + 1] = __uint_as_float(u[c] & 0xffff0000u);
                col[8 + 2 * c]     = __uint_as_float(w[c] << 16);
                col[8 + 2 * c + 1] = __uint_as_float(w[c] & 0xffff0000u);
            }
        }

        float a0 = 0.f, a1 = 0.f, a2 = 0.f, a3 = 0.f;
#pragma unroll
        for (int k = 0; k < 4; k++) {
            a0 = fmaf(v[k],      col[k],      a0);
            a1 = fmaf(v[4 + k],  col[4 + k],  a1);
            a2 = fmaf(v[8 + k],  col[8 + k],  a2);
            a3 = fmaf(v[12 + k], col[12 + k], a3);
        }

        // prefetch step t+4 into the slot just consumed
        if (t + 4 < 128) {
            const int qn = h ? (251 - t) : (t + 4);
            cur[0] = base[qn * 32 + 0];
            cur[1] = base[qn * 32 + 1];
        }

        vp = (a0 + a1) + (a2 + a3);
        const int src = lane & 16;
#pragma unroll
        for (int k = 0; k < 16; k++)
            v[k] = __shfl_sync(0xffffffffu, vp, src | k);
    }

    // Epilogue: Al in lanes 0-15, Ar in lanes 16-31.
    float ar[16], al[16];
#pragma unroll
    for (int k = 0; k < 16; k++)
        ar[k] = __shfl_sync(0xffffffffu, vp, 16 + k);
#pragma unroll
    for (int k = 0; k < 16; k++)
        al[k] = __shfl_sync(0xffffffffu, vp, k);

    if (lane < C_DIM) {
        const float4* Ao = (const float4*)(Aout + lane * 256);
        float acc = 0.f;
#pragma unroll
        for (int l = 0; l < 16; l++) {
            const float a = al[l];
#pragma unroll
            for (int rq = 0; rq < 4; rq++) {
                const float4 x = Ao[l * 4 + rq];
                acc = fmaf(a * x.x, ar[rq * 4 + 0], acc);
                acc = fmaf(a * x.y, ar[rq * 4 + 1], acc);
                acc = fmaf(a * x.z, ar[rq * 4 + 2], acc);
                acc = fmaf(a * x.w, ar[rq * 4 + 3], acc);
            }
        }
        out[b * C_DIM + lane] = acc;
    }
}

// ---------------------------------------------------------------------------
extern "C" void kernel_launch(void* const* d_in, const int* in_sizes, int n_in,
                              void* d_out, int out_size)
{
    const float* x      = (const float*)d_in[0];  // (N, B, d)
    const float* tensor = (const float*)d_in[1];  // (N, D, D, d)
    const float* Aout   = (const float*)d_in[2];  // (C, D, D)
    float* out = (float*)d_out;                   // (B, C)

    pair_kernel<<<NPAIR, 256>>>(tensor, x);
    r_kernel<<<NQUAD, 256>>>();
    q_kernel<<<dim3(8, NQUAD), 256>>>();
    chain_kernel<<<B_DIM, 32>>>(Aout, out);
}

// round 5
// speedup vs baseline: 2.3258x; 2.3258x over previous
#include <cuda_runtime.h>
#include <cuda_bf16.h>

// MPS contraction: pairs -> batch-independent quad-combos (R, fp32) ->
// per-batch quad matrices (Q, bf16) -> boundary-vector chains
// (register prefetch with compile-time slots, smem v-broadcast).
// N=1024 sites, B=256, D=16, d=2, C=10.

#define NPAIR 512
#define NQUAD 256          // quads 0..127 left, 128..255 right (stored transposed)
#define B_DIM 256
#define C_DIM 10

// g_M[p][k*16+j] = float4(M00,M01,M10,M11)[k][j]; transposed storage for p>=256.
__device__ float4 g_M[NPAIR * 256];            // 2 MB
// g_C[p*256+b] = (x0y0, x0y1, x1y0, x1y1)
__device__ float4 g_C[NPAIR * B_DIM];          // 2 MB
// g_R[q*4096 + g*256 + k*16 + j] : combo g = e*4+f, row-major per combo
__device__ float g_R[NQUAD * 16 * 256];        // 4 MB
// g_Qh: bf16, index b*65536 + q*256 + j*16 + k  (column j of quad q, k contiguous)
__device__ __nv_bfloat16 g_Qh[(size_t)B_DIM * NQUAD * 256]; // 32 MB

__device__ __forceinline__ unsigned pack_bf16x2(float lo, float hi) {
    unsigned p;
    asm("cvt.rn.satfinite.bf16x2.f32 %0, %1, %2;" : "=r"(p) : "f"(hi), "f"(lo));
    return p;
}

// ---------------------------------------------------------------------------
// K1: pair matrices (batch-independent) + coefficients. grid=512, block=256.
// ---------------------------------------------------------------------------
__global__ __launch_bounds__(256)
void pair_kernel(const float* __restrict__ tensor, const float* __restrict__ x)
{
    __shared__ float T0[512], T1[512];   // [l][r][dd]
    const int p = blockIdx.x;
    const int t = threadIdx.x;

    const float* base = tensor + (size_t)p * 1024;
    T0[t]       = base[t];
    T0[t + 256] = base[t + 256];
    T1[t]       = base[512 + t];
    T1[t + 256] = base[768 + t];
    __syncthreads();

    const int l = t >> 4;
    const int r = t & 15;
    float a00 = 0.f, a01 = 0.f, a10 = 0.f, a11 = 0.f;
#pragma unroll
    for (int k = 0; k < 16; k++) {
        const float2 a = *(const float2*)&T0[l * 32 + k * 2];
        const float2 b = *(const float2*)&T1[k * 32 + r * 2];
        a00 = fmaf(a.x, b.x, a00);
        a01 = fmaf(a.x, b.y, a01);
        a10 = fmaf(a.y, b.x, a10);
        a11 = fmaf(a.y, b.y, a11);
    }
    const int idx = (p < 256) ? (l * 16 + r) : (r * 16 + l);   // transpose right side
    g_M[p * 256 + idx] = make_float4(a00, a01, a10, a11);

    const float2 xa = *(const float2*)&x[(size_t)(2 * p) * 512 + t * 2];
    const float2 xb = *(const float2*)&x[(size_t)(2 * p) * 512 + 512 + t * 2];
    g_C[p * 256 + t] = make_float4(xa.x * xb.x, xa.x * xb.y, xa.y * xb.x, xa.y * xb.y);
}

// ---------------------------------------------------------------------------
// K2: R_g[q] for all 16 combos. grid=256, block=256 = (16 combos x 16 rows).
// Left (q<128):  R_g = S_{2q,e} @ S_{2q+1,f}
// Right(q>=128): R_g = S_{2q+1,f} @ S_{2q,e}   (transposed quad)
// ---------------------------------------------------------------------------
__global__ __launch_bounds__(256)
void r_kernel()
{
    __shared__ float SA[4][16 * 17], SB[4][16 * 17];
    const int q = blockIdx.x;
    const int t = threadIdx.x;

    {
        const float4 fa = g_M[(2 * q) * 256 + t];
        const float4 fb = g_M[(2 * q + 1) * 256 + t];
        const int k = t >> 4, j = t & 15;
        SA[0][k * 17 + j] = fa.x; SA[1][k * 17 + j] = fa.y;
        SA[2][k * 17 + j] = fa.z; SA[3][k * 17 + j] = fa.w;
        SB[0][k * 17 + j] = fb.x; SB[1][k * 17 + j] = fb.y;
        SB[2][k * 17 + j] = fb.z; SB[3][k * 17 + j] = fb.w;
    }
    __syncthreads();

    const int g  = t >> 4;     // combo e*4+f
    const int kk = t & 15;     // output row
    const int e = g >> 2, f = g & 3;
    const float* P1 = (q < 128) ? SA[e] : SB[f];
    const float* P2 = (q < 128) ? SB[f] : SA[e];

    float acc[16];
#pragma unroll
    for (int j = 0; j < 16; j++) acc[j] = 0.f;
#pragma unroll
    for (int m = 0; m < 16; m++) {
        const float a = P1[kk * 17 + m];
#pragma unroll
        for (int j = 0; j < 16; j++)
            acc[j] = fmaf(a, P2[m * 17 + j], acc[j]);
    }
    float4* dst = (float4*)&g_R[q * 4096 + g * 256 + kk * 16];
    dst[0] = make_float4(acc[0],  acc[1],  acc[2],  acc[3]);
    dst[1] = make_float4(acc[4],  acc[5],  acc[6],  acc[7]);
    dst[2] = make_float4(acc[8],  acc[9],  acc[10], acc[11]);
    dst[3] = make_float4(acc[12], acc[13], acc[14], acc[15]);
}

// ---------------------------------------------------------------------------
// K3: per-batch quad matrices (round-3 structure, bf16 output).
// Qd[b][q] = sum_g (cA_e cB_f) R_g.  grid=(4,256), block=256=(16 bg x 16 cols).
// Thread (bg, j): 4 batches, column j (16 k-values) each.
// ---------------------------------------------------------------------------
__global__ __launch_bounds__(256, 2)
void q_kernel()
{
    __shared__ float Rsh[4096];    // 16 KB
    const int q = blockIdx.y;
    const int t = threadIdx.x;

    {   // stage R for this quad, coalesced
        const float4* src = (const float4*)&g_R[q * 4096 + t * 16];
        float4* dst = (float4*)&Rsh[t * 16];
        dst[0] = src[0]; dst[1] = src[1]; dst[2] = src[2]; dst[3] = src[3];
    }
    __syncthreads();

    const int bg = t >> 4;
    const int j  = t & 15;
    const int b0 = blockIdx.x * 64 + bg * 4;

    float cA[4][4], cB[4][4];
#pragma unroll
    for (int bb = 0; bb < 4; bb++) {
        const float4 a = g_C[(2 * q) * 256 + b0 + bb];
        const float4 c = g_C[(2 * q + 1) * 256 + b0 + bb];
        cA[bb][0] = a.x; cA[bb][1] = a.y; cA[bb][2] = a.z; cA[bb][3] = a.w;
        cB[bb][0] = c.x; cB[bb][1] = c.y; cB[bb][2] = c.z; cB[bb][3] = c.w;
    }

    float acc[4][16];
#pragma unroll
    for (int bb = 0; bb < 4; bb++)
#pragma unroll
        for (int k = 0; k < 16; k++) acc[bb][k] = 0.f;

#pragma unroll
    for (int e = 0; e < 4; e++) {
#pragma unroll
        for (int f = 0; f < 4; f++) {
            const float c0 = cA[0][e] * cB[0][f];
            const float c1 = cA[1][e] * cB[1][f];
            const float c2 = cA[2][e] * cB[2][f];
            const float c3 = cA[3][e] * cB[3][f];
            const float* Rb = &Rsh[(e * 4 + f) * 256 + j];
#pragma unroll
            for (int k = 0; k < 16; k++) {
                const float r = Rb[k * 16];       // conflict-free scalar LDS
                acc[0][k] = fmaf(c0, r, acc[0][k]);
                acc[1][k] = fmaf(c1, r, acc[1][k]);
                acc[2][k] = fmaf(c2, r, acc[2][k]);
                acc[3][k] = fmaf(c3, r, acc[3][k]);
            }
        }
    }

#pragma unroll
    for (int bb = 0; bb < 4; bb++) {
        unsigned w[8];
#pragma unroll
        for (int kp = 0; kp < 8; kp++)
            w[kp] = pack_bf16x2(acc[bb][2 * kp], acc[bb][2 * kp + 1]);
        uint4* dst = (uint4*)(g_Qh + (size_t)(b0 + bb) * 65536 + q * 256 + j * 16);
        dst[0] = make_uint4(w[0], w[1], w[2], w[3]);
        dst[1] = make_uint4(w[4], w[5], w[6], w[7]);
    }
}

// ---------------------------------------------------------------------------
// K4: chains. grid=128 x 64 threads (2 warps). Warp = one batch; lanes 0-15
// left chain (q ascending), lanes 16-31 right chain (q descending, transposed
// quads). Prefetch depth 4 with COMPILE-TIME slot indices (registers, no LDL).
// v broadcast through double-buffered shared memory: 1 STS + 1 syncwarp +
// 4 broadcast LDS.128 per step. No shfl in the main loop.
// ---------------------------------------------------------------------------
__global__ __launch_bounds__(64)
void chain_kernel(const float* __restrict__ Aout, float* __restrict__ out)
{
    __shared__ float vsm[2][2][2][16];   // [warp][pingpong][half][j]

    const int w    = threadIdx.x >> 5;
    const int lane = threadIdx.x & 31;
    const int b    = blockIdx.x * 2 + w;
    const int h    = lane >> 4;
    const int j    = lane & 15;

    // bf16 column base: index b*65536 + q*256 + j*16 + k ; uint4 = 8 bf16
    const uint4* base = (const uint4*)(g_Qh + (size_t)b * 65536 + j * 16);
    // quad q lives at base[q*32 + 0], base[q*32 + 1]

    uint4 buf[4][2];
#pragma unroll
    for (int d = 0; d < 4; d++) {
        const int q = h ? (255 - d) : d;
        buf[d][0] = base[q * 32 + 0];
        buf[d][1] = base[q * 32 + 1];
    }

    // v = e0 in pingpong buffer 0
    vsm[w][0][h][j] = (j == 0) ? 1.f : 0.f;
    __syncwarp();

    for (int T = 0; T < 128; T += 4) {
#pragma unroll
        for (int s = 0; s < 4; s++) {
            const int t  = T + s;
            const int pp = t & 1;

            // broadcast-load current v (4 x LDS.128, conflict-free)
            const float4* vsrc = (const float4*)vsm[w][pp][h];
            const float4 v0 = vsrc[0];
            const float4 v1 = vsrc[1];
            const float4 v2 = vsrc[2];
            const float4 v3 = vsrc[3];

            // decode column j of quad (16 bf16 -> fp32)
            float col[16];
            {
                const unsigned u[4] = {buf[s][0].x, buf[s][0].y, buf[s][0].z, buf[s][0].w};
                const unsigned y[4] = {buf[s][1].x, buf[s][1].y, buf[s][1].z, buf[s][1].w};
#pragma unroll
                for (int c = 0; c < 4; c++) {
                    col[2 * c]         = __uint_as_float(u[c] << 16);
                    col[2 * c + 1]     = __uint_as_float(u[c] & 0xffff0000u);
                    col[8 + 2 * c]     = __uint_as_float(y[c] << 16);
                    col[8 + 2 * c + 1] = __uint_as_float(y[c] & 0xffff0000u);
                }
            }

            float a0 = 0.f, a1 = 0.f, a2 = 0.f, a3 = 0.f;
            a0 = fmaf(v0.x, col[0],  a0);  a0 = fmaf(v0.y, col[1],  a0);
            a0 = fmaf(v0.z, col[2],  a0);  a0 = fmaf(v0.w, col[3],  a0);
            a1 = fmaf(v1.x, col[4],  a1);  a1 = fmaf(v1.y, col[5],  a1);
            a1 = fmaf(v1.z, col[6],  a1);  a1 = fmaf(v1.w, col[7],  a1);
            a2 = fmaf(v2.x, col[8],  a2);  a2 = fmaf(v2.y, col[9],  a2);
            a2 = fmaf(v2.z, col[10], a2);  a2 = fmaf(v2.w, col[11], a2);
            a3 = fmaf(v3.x, col[12], a3);  a3 = fmaf(v3.y, col[13], a3);
            a3 = fmaf(v3.z, col[14], a3);  a3 = fmaf(v3.w, col[15], a3);

            // prefetch step t+4 into slot s (compile-time index)
            if (t + 4 < 128) {
                const int qn = h ? (251 - t) : (t + 4);
                buf[s][0] = base[qn * 32 + 0];
                buf[s][1] = base[qn * 32 + 1];
            }

            const float vp = (a0 + a1) + (a2 + a3);
            // write next v to the other pingpong buffer.
            // WAR on vsm[pp^1] vs prior step's reads is protected by the
            // prior step's trailing __syncwarp; RAW for the next step's
            // reads is protected by this one.
            vsm[w][pp ^ 1][h][j] = vp;
            __syncwarp();
        }
    }

    // After t=127 (pp=1), final vectors live in vsm[w][0]:
    //   Al = vsm[w][0][0][:], Ar = vsm[w][0][1][:]
    if (lane < C_DIM) {
        const float* Al = vsm[w][0][0];
        const float* Ar = vsm[w][0][1];
        const float4* Ao = (const float4*)(Aout + lane * 256);
        float acc = 0.f;
#pragma unroll
        for (int l = 0; l < 16; l++) {
            const float a = Al[l];
#pragma unroll
            for (int rq = 0; rq < 4; rq++) {
                const float4 x = Ao[l * 4 + rq];
                acc = fmaf(a * x.x, Ar[rq * 4 + 0], acc);
                acc = fmaf(a * x.y, Ar[rq * 4 + 1], acc);
                acc = fmaf(a * x.z, Ar[rq * 4 + 2], acc);
                acc = fmaf(a * x.w, Ar[rq * 4 + 3], acc);
            }
        }
        out[b * C_DIM + lane] = acc;
    }
}

// ---------------------------------------------------------------------------
extern "C" void kernel_launch(void* const* d_in, const int* in_sizes, int n_in,
                              void* d_out, int out_size)
{
    const float* x      = (const float*)d_in[0];  // (N, B, d)
    const float* tensor = (const float*)d_in[1];  // (N, D, D, d)
    const float* Aout   = (const float*)d_in[2];  // (C, D, D)
    float* out = (float*)d_out;                   // (B, C)

    pair_kernel<<<NPAIR, 256>>>(tensor, x);
    r_kernel<<<NQUAD, 256>>>();
    q_kernel<<<dim3(4, NQUAD), 256>>>();
    chain_kernel<<<B_DIM / 2, 64>>>(Aout, out);
}

// round 6
// speedup vs baseline: 2.6581x; 1.1429x over previous
#include <cuda_runtime.h>
#include <cuda_bf16.h>

// MPS contraction: fused pair+quad-combo kernel (R, fp32) ->
// per-batch quad matrices (Q, bf16, coeffs from x directly) ->
// boundary-vector chains (depth-8 register prefetch, smem v-broadcast).
// N=1024 sites, B=256, D=16, d=2, C=10.

#define NQUAD 256          // quads 0..127 left, 128..255 right (stored transposed)
#define B_DIM 256
#define C_DIM 10

// g_R[q*4096 + g*256 + k*16 + j] : combo g = e*4+f, row-major per combo
__device__ float g_R[NQUAD * 16 * 256];        // 4 MB
// g_Qh: bf16, index b*65536 + q*256 + j*16 + k  (column j of quad q, k contiguous)
__device__ __nv_bfloat16 g_Qh[(size_t)B_DIM * NQUAD * 256]; // 32 MB

__device__ __forceinline__ unsigned pack_bf16x2(float lo, float hi) {
    unsigned p;
    asm("cvt.rn.satfinite.bf16x2.f32 %0, %1, %2;" : "=r"(p) : "f"(hi), "f"(lo));
    return p;
}

// ---------------------------------------------------------------------------
// K1 (fused pair + combo): one block per quad q (sites 4q..4q+3).
// Stage 1: pair matrices SA_e = T[4q,d1] @ T[4q+1,d2], SB_f likewise for
//          sites 4q+2/4q+3 (e,f = d1*2+d2), written TRANSPOSED for q>=128.
// Stage 2: R_g = SA_e @ SB_f (left) or SB_f @ SA_e (right) for all 16 combos,
//          identical to the validated r_kernel inner loop.
// grid=256, block=256.
// ---------------------------------------------------------------------------
__global__ __launch_bounds__(256)
void pr_kernel(const float* __restrict__ tensor)
{
    __shared__ float T[4][1024];                 // [site][l*32 + r*2 + dd], 16 KB
    __shared__ float SA[4][16 * 17], SB[4][16 * 17];
    const int q = blockIdx.x;
    const int t = threadIdx.x;

    {   // load 4 sites = 4096 floats, coalesced float4
        const float4* src = (const float4*)(tensor + (size_t)q * 4096);
        float4* dst = (float4*)&T[0][0];
#pragma unroll
        for (int i = 0; i < 4; i++) dst[t + 256 * i] = src[t + 256 * i];
    }
    __syncthreads();

    const int l = t >> 4;
    const int r = t & 15;
    // pair A = sites (4q, 4q+1); pair B = sites (4q+2, 4q+3)
    float pa[4] = {0.f, 0.f, 0.f, 0.f};
    float pb[4] = {0.f, 0.f, 0.f, 0.f};
#pragma unroll
    for (int k = 0; k < 16; k++) {
        const float2 a0 = *(const float2*)&T[0][l * 32 + k * 2];
        const float2 a1 = *(const float2*)&T[1][k * 32 + r * 2];
        pa[0] = fmaf(a0.x, a1.x, pa[0]);
        pa[1] = fmaf(a0.x, a1.y, pa[1]);
        pa[2] = fmaf(a0.y, a1.x, pa[2]);
        pa[3] = fmaf(a0.y, a1.y, pa[3]);
        const float2 b0 = *(const float2*)&T[2][l * 32 + k * 2];
        const float2 b1 = *(const float2*)&T[3][k * 32 + r * 2];
        pb[0] = fmaf(b0.x, b1.x, pb[0]);
        pb[1] = fmaf(b0.x, b1.y, pb[1]);
        pb[2] = fmaf(b0.y, b1.x, pb[2]);
        pb[3] = fmaf(b0.y, b1.y, pb[3]);
    }
    __syncthreads();   // T reads done before SA/SB overwrite nothing (distinct smem) -- ordering for stage 2 reads
    const int idx = (q < 128) ? (l * 17 + r) : (r * 17 + l);   // transpose right side
#pragma unroll
    for (int e = 0; e < 4; e++) { SA[e][idx] = pa[e]; SB[e][idx] = pb[e]; }
    __syncthreads();

    const int g  = t >> 4;     // combo e*4+f
    const int kk = t & 15;     // output row
    const int e = g >> 2, f = g & 3;
    const float* P1 = (q < 128) ? SA[e] : SB[f];
    const float* P2 = (q < 128) ? SB[f] : SA[e];

    float acc[16];
#pragma unroll
    for (int j = 0; j < 16; j++) acc[j] = 0.f;
#pragma unroll
    for (int m = 0; m < 16; m++) {
        const float a = P1[kk * 17 + m];
#pragma unroll
        for (int j = 0; j < 16; j++)
            acc[j] = fmaf(a, P2[m * 17 + j], acc[j]);
    }
    float4* dst = (float4*)&g_R[q * 4096 + g * 256 + kk * 16];
    dst[0] = make_float4(acc[0],  acc[1],  acc[2],  acc[3]);
    dst[1] = make_float4(acc[4],  acc[5],  acc[6],  acc[7]);
    dst[2] = make_float4(acc[8],  acc[9],  acc[10], acc[11]);
    dst[3] = make_float4(acc[12], acc[13], acc[14], acc[15]);
}

// ---------------------------------------------------------------------------
// K2: per-batch quad matrices, coefficients computed from x directly.
// Qd[b][q] = sum_g (cA_e cB_f) R_g.  grid=(4,256), block=256=(16 bg x 16 cols).
// Thread (bg, j): 4 batches, column j (16 k-values) each. Output bf16.
// ---------------------------------------------------------------------------
__global__ __launch_bounds__(256, 2)
void q_kernel(const float* __restrict__ x)
{
    __shared__ float Rsh[4096];     // 16 KB
    __shared__ float2 xs[4][64];    // x[4q+s][b0q + 0..63][:]
    const int q = blockIdx.y;
    const int t = threadIdx.x;

    {   // stage R for this quad, coalesced
        const float4* src = (const float4*)&g_R[q * 4096 + t * 16];
        float4* dst = (float4*)&Rsh[t * 16];
        dst[0] = src[0]; dst[1] = src[1]; dst[2] = src[2]; dst[3] = src[3];
    }
    {   // stage x: 4 sites x 64 batches, coalesced float2
        const int s = t >> 6, i = t & 63;
        xs[s][i] = ((const float2*)x)[(size_t)(4 * q + s) * 256 + blockIdx.x * 64 + i];
    }
    __syncthreads();

    const int bg = t >> 4;
    const int j  = t & 15;
    const int b0 = blockIdx.x * 64 + bg * 4;

    float cA[4][4], cB[4][4];
#pragma unroll
    for (int bb = 0; bb < 4; bb++) {
        const int bl = bg * 4 + bb;
        const float2 x0 = xs[0][bl];
        const float2 x1 = xs[1][bl];
        const float2 x2 = xs[2][bl];
        const float2 x3 = xs[3][bl];
        cA[bb][0] = x0.x * x1.x; cA[bb][1] = x0.x * x1.y;
        cA[bb][2] = x0.y * x1.x; cA[bb][3] = x0.y * x1.y;
        cB[bb][0] = x2.x * x3.x; cB[bb][1] = x2.x * x3.y;
        cB[bb][2] = x2.y * x3.x; cB[bb][3] = x2.y * x3.y;
    }

    float acc[4][16];
#pragma unroll
    for (int bb = 0; bb < 4; bb++)
#pragma unroll
        for (int k = 0; k < 16; k++) acc[bb][k] = 0.f;

#pragma unroll
    for (int e = 0; e < 4; e++) {
#pragma unroll
        for (int f = 0; f < 4; f++) {
            const float c0 = cA[0][e] * cB[0][f];
            const float c1 = cA[1][e] * cB[1][f];
            const float c2 = cA[2][e] * cB[2][f];
            const float c3 = cA[3][e] * cB[3][f];
            const float* Rb = &Rsh[(e * 4 + f) * 256 + j];
#pragma unroll
            for (int k = 0; k < 16; k++) {
                const float r = Rb[k * 16];       // broadcast/conflict-free LDS
                acc[0][k] = fmaf(c0, r, acc[0][k]);
                acc[1][k] = fmaf(c1, r, acc[1][k]);
                acc[2][k] = fmaf(c2, r, acc[2][k]);
                acc[3][k] = fmaf(c3, r, acc[3][k]);
            }
        }
    }

#pragma unroll
    for (int bb = 0; bb < 4; bb++) {
        unsigned w[8];
#pragma unroll
        for (int kp = 0; kp < 8; kp++)
            w[kp] = pack_bf16x2(acc[bb][2 * kp], acc[bb][2 * kp + 1]);
        uint4* dst = (uint4*)(g_Qh + (size_t)(b0 + bb) * 65536 + q * 256 + j * 16);
        dst[0] = make_uint4(w[0], w[1], w[2], w[3]);
        dst[1] = make_uint4(w[4], w[5], w[6], w[7]);
    }
}

// ---------------------------------------------------------------------------
// K3: chains. grid=128 x 64 threads (2 warps). Warp = one batch; lanes 0-15
// left chain (q ascending), lanes 16-31 right chain (q descending, transposed
// quads). Prefetch depth 8 with COMPILE-TIME slot indices (pure registers).
// v broadcast through double-buffered shared memory: 1 STS + 1 syncwarp +
// 4 broadcast LDS.128 per step.
// ---------------------------------------------------------------------------
__global__ __launch_bounds__(64)
void chain_kernel(const float* __restrict__ Aout, float* __restrict__ out)
{
    __shared__ float vsm[2][2][2][16];   // [warp][pingpong][half][j]

    const int w    = threadIdx.x >> 5;
    const int lane = threadIdx.x & 31;
    const int b    = blockIdx.x * 2 + w;
    const int h    = lane >> 4;
    const int j    = lane & 15;

    // bf16 column base: index b*65536 + q*256 + j*16 + k ; uint4 = 8 bf16
    const uint4* base = (const uint4*)(g_Qh + (size_t)b * 65536 + j * 16);

    uint4 buf[8][2];
#pragma unroll
    for (int d = 0; d < 8; d++) {
        const int q = h ? (255 - d) : d;
        buf[d][0] = base[q * 32 + 0];
        buf[d][1] = base[q * 32 + 1];
    }

    // v = e0 in pingpong buffer 0
    vsm[w][0][h][j] = (j == 0) ? 1.f : 0.f;
    __syncwarp();

    for (int T = 0; T < 128; T += 8) {
#pragma unroll
        for (int s = 0; s < 8; s++) {
            const int t  = T + s;
            const int pp = t & 1;

            // broadcast-load current v (4 x LDS.128, conflict-free)
            const float4* vsrc = (const float4*)vsm[w][pp][h];
            const float4 v0 = vsrc[0];
            const float4 v1 = vsrc[1];
            const float4 v2 = vsrc[2];
            const float4 v3 = vsrc[3];

            // decode column j of quad (16 bf16 -> fp32)
            float col[16];
            {
                const unsigned u[4] = {buf[s][0].x, buf[s][0].y, buf[s][0].z, buf[s][0].w};
                const unsigned y[4] = {buf[s][1].x, buf[s][1].y, buf[s][1].z, buf[s][1].w};
#pragma unroll
                for (int c = 0; c < 4; c++) {
                    col[2 * c]         = __uint_as_float(u[c] << 16);
                    col[2 * c + 1]     = __uint_as_float(u[c] & 0xffff0000u);
                    col[8 + 2 * c]     = __uint_as_float(y[c] << 16);
                    col[8 + 2 * c + 1] = __uint_as_float(y[c] & 0xffff0000u);
                }
            }

            float a0 = 0.f, a1 = 0.f, a2 = 0.f, a3 = 0.f;
            a0 = fmaf(v0.x, col[0],  a0);  a0 = fmaf(v0.y, col[1],  a0);
            a0 = fmaf(v0.z, col[2],  a0);  a0 = fmaf(v0.w, col[3],  a0);
            a1 = fmaf(v1.x, col[4],  a1);  a1 = fmaf(v1.y, col[5],  a1);
            a1 = fmaf(v1.z, col[6],  a1);  a1 = fmaf(v1.w, col[7],  a1);
            a2 = fmaf(v2.x, col[8],  a2);  a2 = fmaf(v2.y, col[9],  a2);
            a2 = fmaf(v2.z, col[10], a2);  a2 = fmaf(v2.w, col[11], a2);
            a3 = fmaf(v3.x, col[12], a3);  a3 = fmaf(v3.y, col[13], a3);
            a3 = fmaf(v3.z, col[14], a3);  a3 = fmaf(v3.w, col[15], a3);

            // prefetch step t+8 into slot s (compile-time index)
            if (t + 8 < 128) {
                const int qn = h ? (247 - t) : (t + 8);
                buf[s][0] = base[qn * 32 + 0];
                buf[s][1] = base[qn * 32 + 1];
            }

            const float vp = (a0 + a1) + (a2 + a3);
            vsm[w][pp ^ 1][h][j] = vp;
            __syncwarp();
        }
    }

    // After t=127 (pp=1), final vectors live in vsm[w][0]:
    //   Al = vsm[w][0][0][:], Ar = vsm[w][0][1][:]
    if (lane < C_DIM) {
        const float* Al = vsm[w][0][0];
        const float* Ar = vsm[w][0][1];
        const float4* Ao = (const float4*)(Aout + lane * 256);
        float acc = 0.f;
#pragma unroll
        for (int l = 0; l < 16; l++) {
            const float a = Al[l];
#pragma unroll
            for (int rq = 0; rq < 4; rq++) {
                const float4 xv = Ao[l * 4 + rq];
                acc = fmaf(a * xv.x, Ar[rq * 4 + 0], acc);
                acc = fmaf(a * xv.y, Ar[rq * 4 + 1], acc);
                acc = fmaf(a * xv.z, Ar[rq * 4 + 2], acc);
                acc = fmaf(a * xv.w, Ar[rq * 4 + 3], acc);
            }
        }
        out[b * C_DIM + lane] = acc;
    }
}

// ---------------------------------------------------------------------------
extern "C" void kernel_launch(void* const* d_in, const int* in_sizes, int n_in,
                              void* d_out, int out_size)
{
    const float* x      = (const float*)d_in[0];  // (N, B, d)
    const float* tensor = (const float*)d_in[1];  // (N, D, D, d)
    const float* Aout   = (const float*)d_in[2];  // (C, D, D)
    float* out = (float*)d_out;                   // (B, C)

    pr_kernel<<<NQUAD, 256>>>(tensor);
    q_kernel<<<dim3(4, NQUAD), 256>>>(x);
    chain_kernel<<<B_DIM / 2, 64>>>(Aout, out);
}

// round 7
// speedup vs baseline: 2.9519x; 1.1105x over previous
#include <cuda_runtime.h>
#include <cuda_bf16.h>

// MPS contraction, fully fused producer:
//   prq_kernel: tensor -> pair matrices -> quad combos R (smem, padded) ->
//               per-batch quad matrices Q (bf16, packed f32x2 FMA)
//   chain_kernel: register-resident boundary-vector chains, shfl broadcast,
//                 depth-8 compile-time register prefetch.
// N=1024 sites, B=256, D=16, d=2, C=10.

#define NQUAD 256          // quads 0..127 left, 128..255 right (stored transposed)
#define B_DIM 256
#define C_DIM 10

// g_Qh: bf16, index b*65536 + q*256 + j*16 + k  (column j of quad q, k contiguous)
__device__ __nv_bfloat16 g_Qh[(size_t)B_DIM * NQUAD * 256]; // 32 MB

// ---- packed helpers --------------------------------------------------------
__device__ __forceinline__ unsigned long long pack2(float lo, float hi) {
    unsigned long long r;
    asm("mov.b64 %0, {%1, %2};" : "=l"(r) : "f"(lo), "f"(hi));
    return r;
}
__device__ __forceinline__ void fma2(unsigned long long& d,
                                     unsigned long long a, unsigned long long b) {
    asm("fma.rn.f32x2 %0, %1, %2, %0;" : "+l"(d) : "l"(a), "l"(b));
}
// u64 (lo = k even, hi = k odd) -> bf16x2 word with k-even in low half
__device__ __forceinline__ unsigned cvt_bf16x2(unsigned long long v) {
    float lo, hi; unsigned p;
    asm("mov.b64 {%0, %1}, %2;" : "=f"(lo), "=f"(hi) : "l"(v));
    asm("cvt.rn.satfinite.bf16x2.f32 %0, %1, %2;" : "=r"(p) : "f"(hi), "f"(lo));
    return p;
}

// ---------------------------------------------------------------------------
// K1 (fused): one block per quad q (sites 4q..4q+3), 256 threads.
// Stage A: pair matrices SA_e = T[4q,d1]@T[4q+1,d2], SB_f for sites 4q+2/3,
//          written transposed for q>=128.
// Stage B: R_g (g=e*4+f) columns into padded smem Rsh[g*288 + j*18 + k].
// Stage C: 4 slices x 64 batches: Qd[b][q] = sum_g (cA_e cB_f) R_g, packed
//          f32x2 accumulation, bf16 output. Thread (bg,j): 4 batches, col j.
// ---------------------------------------------------------------------------
__global__ __launch_bounds__(256)
void prq_kernel(const float* __restrict__ tensor, const float* __restrict__ x)
{
    __shared__ float T[4][1024];                 // 16 KB  [site][l*32 + r*2 + dd]
    __shared__ float SA[4][16 * 17], SB[4][16 * 17];   // 8.5 KB
    __shared__ float Rsh[16 * 288];              // 18 KB, [g][j*18 + k]
    __shared__ float2 xs[4][64];                 // 2 KB   [site][batch-in-slice]

    const int q = blockIdx.x;
    const int t = threadIdx.x;

    // ---- Stage A: load 4 sites, compute pair matrices ----
    {
        const float4* src = (const float4*)(tensor + (size_t)q * 4096);
        float4* dst = (float4*)&T[0][0];
#pragma unroll
        for (int i = 0; i < 4; i++) dst[t + 256 * i] = src[t + 256 * i];
    }
    __syncthreads();

    const int l = t >> 4;
    const int r = t & 15;
    float pa[4] = {0.f, 0.f, 0.f, 0.f};
    float pb[4] = {0.f, 0.f, 0.f, 0.f};
#pragma unroll
    for (int k = 0; k < 16; k++) {
        const float2 a0 = *(const float2*)&T[0][l * 32 + k * 2];
        const float2 a1 = *(const float2*)&T[1][k * 32 + r * 2];
        pa[0] = fmaf(a0.x, a1.x, pa[0]);
        pa[1] = fmaf(a0.x, a1.y, pa[1]);
        pa[2] = fmaf(a0.y, a1.x, pa[2]);
        pa[3] = fmaf(a0.y, a1.y, pa[3]);
        const float2 b0 = *(const float2*)&T[2][l * 32 + k * 2];
        const float2 b1 = *(const float2*)&T[3][k * 32 + r * 2];
        pb[0] = fmaf(b0.x, b1.x, pb[0]);
        pb[1] = fmaf(b0.x, b1.y, pb[1]);
        pb[2] = fmaf(b0.y, b1.x, pb[2]);
        pb[3] = fmaf(b0.y, b1.y, pb[3]);
    }
    __syncthreads();
    const int idx = (q < 128) ? (l * 17 + r) : (r * 17 + l);   // transpose right side
#pragma unroll
    for (int e = 0; e < 4; e++) { SA[e][idx] = pa[e]; SB[e][idx] = pb[e]; }
    __syncthreads();

    // ---- Stage B: R columns into padded smem ----
    {
        const int g  = t >> 4;     // combo e*4+f
        const int jj = t & 15;     // output column
        const int e = g >> 2, f = g & 3;
        const float* P1 = (q < 128) ? SA[e] : SB[f];
        const float* P2 = (q < 128) ? SB[f] : SA[e];

        float acc[16];
#pragma unroll
        for (int k = 0; k < 16; k++) acc[k] = 0.f;
#pragma unroll
        for (int m = 0; m < 16; m++) {
            const float bsc = P2[m * 17 + jj];
#pragma unroll
            for (int k = 0; k < 16; k++)
                acc[k] = fmaf(P1[k * 17 + m], bsc, acc[k]);
        }
        float2* dst = (float2*)&Rsh[g * 288 + jj * 18];
#pragma unroll
        for (int kp = 0; kp < 8; kp++)
            dst[kp] = make_float2(acc[2 * kp], acc[2 * kp + 1]);
    }
    __syncthreads();

    // ---- Stage C: 4 slices of 64 batches ----
    const int bg = t >> 4;      // 16 groups of 4 batches
    const int j  = t & 15;

    for (int s8 = 0; s8 < 4; s8++) {
        // stage x for this slice: 4 sites x 64 batches, coalesced float2
        {
            const int s = t >> 6, i = t & 63;
            xs[s][i] = ((const float2*)x)[(size_t)(4 * q + s) * 256 + s8 * 64 + i];
        }
        __syncthreads();

        const int b0 = s8 * 64 + bg * 4;

        float cA[4][4], cB[4][4];
#pragma unroll
        for (int bb = 0; bb < 4; bb++) {
            const int bl = bg * 4 + bb;
            const float2 x0 = xs[0][bl];
            const float2 x1 = xs[1][bl];
            const float2 x2 = xs[2][bl];
            const float2 x3 = xs[3][bl];
            cA[bb][0] = x0.x * x1.x; cA[bb][1] = x0.x * x1.y;
            cA[bb][2] = x0.y * x1.x; cA[bb][3] = x0.y * x1.y;
            cB[bb][0] = x2.x * x3.x; cB[bb][1] = x2.x * x3.y;
            cB[bb][2] = x2.y * x3.x; cB[bb][3] = x2.y * x3.y;
        }

        unsigned long long acc[4][8];
#pragma unroll
        for (int bb = 0; bb < 4; bb++)
#pragma unroll
            for (int kp = 0; kp < 8; kp++) acc[bb][kp] = 0ull;

#pragma unroll
        for (int e = 0; e < 4; e++) {
#pragma unroll
            for (int f = 0; f < 4; f++) {
                const unsigned long long c0 = pack2(cA[0][e] * cB[0][f], cA[0][e] * cB[0][f]);
                const unsigned long long c1 = pack2(cA[1][e] * cB[1][f], cA[1][e] * cB[1][f]);
                const unsigned long long c2 = pack2(cA[2][e] * cB[2][f], cA[2][e] * cB[2][f]);
                const unsigned long long c3 = pack2(cA[3][e] * cB[3][f], cA[3][e] * cB[3][f]);
                const unsigned long long* Rp =
                    (const unsigned long long*)&Rsh[(e * 4 + f) * 288 + j * 18];
#pragma unroll
                for (int kp = 0; kp < 8; kp++) {
                    const unsigned long long rr = Rp[kp];   // conflict-free LDS.64
                    fma2(acc[0][kp], c0, rr);
                    fma2(acc[1][kp], c1, rr);
                    fma2(acc[2][kp], c2, rr);
                    fma2(acc[3][kp], c3, rr);
                }
            }
        }

#pragma unroll
        for (int bb = 0; bb < 4; bb++) {
            unsigned w[8];
#pragma unroll
            for (int kp = 0; kp < 8; kp++) w[kp] = cvt_bf16x2(acc[bb][kp]);
            uint4* dst = (uint4*)(g_Qh + (size_t)(b0 + bb) * 65536 + q * 256 + j * 16);
            dst[0] = make_uint4(w[0], w[1], w[2], w[3]);
            dst[1] = make_uint4(w[4], w[5], w[6], w[7]);
        }
        __syncthreads();   // protect xs before next slice overwrites
    }
}

// ---------------------------------------------------------------------------
// K2: chains. grid=256 single-warp blocks. Block = one batch; lanes 0-15 left
// chain (q ascending), lanes 16-31 right chain (q descending, transposed
// quads). Depth-8 register prefetch with compile-time slot indices.
// v register-resident; broadcast via 16 independent shfls (no smem, no sync).
// ---------------------------------------------------------------------------
__global__ __launch_bounds__(32)
void chain_kernel(const float* __restrict__ Aout, float* __restrict__ out)
{
    const int b    = blockIdx.x;
    const int lane = threadIdx.x;
    const int h    = lane >> 4;
    const int j    = lane & 15;

    // bf16 column base: index b*65536 + q*256 + j*16 + k ; uint4 = 8 bf16
    const uint4* base = (const uint4*)(g_Qh + (size_t)b * 65536 + j * 16);

    uint4 buf[8][2];
#pragma unroll
    for (int d = 0; d < 8; d++) {
        const int q = h ? (255 - d) : d;
        buf[d][0] = base[q * 32 + 0];
        buf[d][1] = base[q * 32 + 1];
    }

    float v[16];
#pragma unroll
    for (int k = 0; k < 16; k++) v[k] = (k == 0) ? 1.f : 0.f;
    float vp = 0.f;

    for (int T = 0; T < 128; T += 8) {
#pragma unroll
        for (int s = 0; s < 8; s++) {
            const int t = T + s;

            // decode column j of quad (16 bf16 -> fp32), off critical path
            float col[16];
            {
                const unsigned u[4] = {buf[s][0].x, buf[s][0].y, buf[s][0].z, buf[s][0].w};
                const unsigned y[4] = {buf[s][1].x, buf[s][1].y, buf[s][1].z, buf[s][1].w};
#pragma unroll
                for (int c = 0; c < 4; c++) {
                    col[2 * c]         = __uint_as_float(u[c] << 16);
                    col[2 * c + 1]     = __uint_as_float(u[c] & 0xffff0000u);
                    col[8 + 2 * c]     = __uint_as_float(y[c] << 16);
                    col[8 + 2 * c + 1] = __uint_as_float(y[c] & 0xffff0000u);
                }
            }

            float a0 = 0.f, a1 = 0.f, a2 = 0.f, a3 = 0.f;
#pragma unroll
            for (int k = 0; k < 4; k++) {
                a0 = fmaf(v[k],      col[k],      a0);
                a1 = fmaf(v[4 + k],  col[4 + k],  a1);
                a2 = fmaf(v[8 + k],  col[8 + k],  a2);
                a3 = fmaf(v[12 + k], col[12 + k], a3);
            }

            // prefetch step t+8 into slot s (compile-time index, stays in regs)
            if (t + 8 < 128) {
                const int qn = h ? (247 - t) : (t + 8);
                buf[s][0] = base[qn * 32 + 0];
                buf[s][1] = base[qn * 32 + 1];
            }

            vp = (a0 + a1) + (a2 + a3);
            const int src = lane & 16;
#pragma unroll
            for (int k = 0; k < 16; k++)
                v[k] = __shfl_sync(0xffffffffu, vp, src | k);
        }
    }

    // Epilogue: Al in lanes 0-15 (vp), Ar in lanes 16-31 (vp).
    float al[16], ar[16];
#pragma unroll
    for (int k = 0; k < 16; k++)
        al[k] = __shfl_sync(0xffffffffu, vp, k);
#pragma unroll
    for (int k = 0; k < 16; k++)
        ar[k] = __shfl_sync(0xffffffffu, vp, 16 + k);

    if (lane < C_DIM) {
        const float4* Ao = (const float4*)(Aout + lane * 256);
        float acc = 0.f;
#pragma unroll
        for (int l = 0; l < 16; l++) {
            const float a = al[l];
#pragma unroll
            for (int rq = 0; rq < 4; rq++) {
                const float4 xv = Ao[l * 4 + rq];
                acc = fmaf(a * xv.x, ar[rq * 4 + 0], acc);
                acc = fmaf(a * xv.y, ar[rq * 4 + 1], acc);
                acc = fmaf(a * xv.z, ar[rq * 4 + 2], acc);
                acc = fmaf(a * xv.w, ar[rq * 4 + 3], acc);
            }
        }
        out[b * C_DIM + lane] = acc;
    }
}

// ---------------------------------------------------------------------------
extern "C" void kernel_launch(void* const* d_in, const int* in_sizes, int n_in,
                              void* d_out, int out_size)
{
    const float* x      = (const float*)d_in[0];  // (N, B, d)
    const float* tensor = (const float*)d_in[1];  // (N, D, D, d)
    const float* Aout   = (const float*)d_in[2];  // (C, D, D)
    float* out = (float*)d_out;                   // (B, C)

    prq_kernel<<<NQUAD, 256>>>(tensor, x);
    chain_kernel<<<B_DIM, 32>>>(Aout, out);
}

// round 8
// speedup vs baseline: 3.0317x; 1.0270x over previous
#include <cuda_runtime.h>
#include <cuda_bf16.h>

// MPS contraction:
//   prq_kernel: tensor -> pair matrices -> quad combos R (smem) ->
//               per-batch quad matrices Q (bf16, packed f32x2 FMA),
//               barrier-free batch loop.
//   chain_kernel: boundary-vector chains in packed bf16 (HFMA2), smem
//                 ping-pong v broadcast, depth-8 register prefetch.
// N=1024 sites, B=256, D=16, d=2, C=10.

#define NQUAD 256          // quads 0..127 left, 128..255 right (stored transposed)
#define B_DIM 256
#define C_DIM 10

// g_Qh: bf16, index b*65536 + q*256 + j*16 + k  (column j of quad q, k pairs
// packed (k even = low half) by cvt_bf16x2)
__device__ __nv_bfloat16 g_Qh[(size_t)B_DIM * NQUAD * 256]; // 32 MB

// ---- packed helpers --------------------------------------------------------
__device__ __forceinline__ unsigned long long pack2(float lo, float hi) {
    unsigned long long r;
    asm("mov.b64 %0, {%1, %2};" : "=l"(r) : "f"(lo), "f"(hi));
    return r;
}
__device__ __forceinline__ void fma2(unsigned long long& d,
                                     unsigned long long a, unsigned long long b) {
    asm("fma.rn.f32x2 %0, %1, %2, %0;" : "+l"(d) : "l"(a), "l"(b));
}
// u64 (lo = k even, hi = k odd) -> bf16x2 word with k-even in low half
__device__ __forceinline__ unsigned cvt_bf16x2(unsigned long long v) {
    float lo, hi; unsigned p;
    asm("mov.b64 {%0, %1}, %2;" : "=f"(lo), "=f"(hi) : "l"(v));
    asm("cvt.rn.satfinite.bf16x2.f32 %0, %1, %2;" : "=r"(p) : "f"(hi), "f"(lo));
    return p;
}
__device__ __forceinline__ unsigned hmul2(unsigned a, unsigned b) {
    unsigned r;
    asm("mul.rn.bf16x2 %0, %1, %2;" : "=r"(r) : "r"(a), "r"(b));
    return r;
}
__device__ __forceinline__ void hfma2(unsigned& d, unsigned a, unsigned b) {
    asm("fma.rn.bf16x2 %0, %1, %2, %0;" : "+r"(d) : "r"(a), "r"(b));
}
__device__ __forceinline__ unsigned hadd2(unsigned a, unsigned b) {
    unsigned r;
    asm("add.rn.bf16x2 %0, %1, %2;" : "=r"(r) : "r"(a), "r"(b));
    return r;
}

// ---------------------------------------------------------------------------
// K1 (fused): one block per quad q (sites 4q..4q+3), 256 threads.
// Stage A: pair matrices SA_e = T[4q,d1]@T[4q+1,d2], SB_f for sites 4q+2/3,
//          written transposed for q>=128. x for all 256 batches staged into
//          the dead T buffer.
// Stage B: R_g (g=e*4+f) columns into padded smem Rsh[g*288 + j*18 + k].
// Stage C: 4 barrier-free slices x 64 batches:
//          Qd[b][q] = sum_g (cA_e cB_f) R_g, packed f32x2, bf16 output.
// ---------------------------------------------------------------------------
__global__ __launch_bounds__(256)
void prq_kernel(const float* __restrict__ tensor, const float* __restrict__ x)
{
    __shared__ float T[4][1024];                 // 16 KB  [site][l*32 + r*2 + dd]
    __shared__ float SA[4][16 * 17], SB[4][16 * 17];   // 8.5 KB
    __shared__ float Rsh[16 * 288];              // 18 KB, [g][j*18 + k]

    // xs aliases T (dead after stage A): [site][batch] float2, 8 KB
    float2* xs = (float2*)&T[0][0];

    const int q = blockIdx.x;
    const int t = threadIdx.x;

    // ---- Stage A: load 4 sites, compute pair matrices ----
    {
        const float4* src = (const float4*)(tensor + (size_t)q * 4096);
        float4* dst = (float4*)&T[0][0];
#pragma unroll
        for (int i = 0; i < 4; i++) dst[t + 256 * i] = src[t + 256 * i];
    }
    __syncthreads();

    const int l = t >> 4;
    const int r = t & 15;
    float pa[4] = {0.f, 0.f, 0.f, 0.f};
    float pb[4] = {0.f, 0.f, 0.f, 0.f};
#pragma unroll
    for (int k = 0; k < 16; k++) {
        const float2 a0 = *(const float2*)&T[0][l * 32 + k * 2];
        const float2 a1 = *(const float2*)&T[1][k * 32 + r * 2];
        pa[0] = fmaf(a0.x, a1.x, pa[0]);
        pa[1] = fmaf(a0.x, a1.y, pa[1]);
        pa[2] = fmaf(a0.y, a1.x, pa[2]);
        pa[3] = fmaf(a0.y, a1.y, pa[3]);
        const float2 b0 = *(const float2*)&T[2][l * 32 + k * 2];
        const float2 b1 = *(const float2*)&T[3][k * 32 + r * 2];
        pb[0] = fmaf(b0.x, b1.x, pb[0]);
        pb[1] = fmaf(b0.x, b1.y, pb[1]);
        pb[2] = fmaf(b0.y, b1.x, pb[2]);
        pb[3] = fmaf(b0.y, b1.y, pb[3]);
    }
    __syncthreads();   // all T reads complete; T becomes xs storage below

    const int idx = (q < 128) ? (l * 17 + r) : (r * 17 + l);   // transpose right side
#pragma unroll
    for (int e = 0; e < 4; e++) { SA[e][idx] = pa[e]; SB[e][idx] = pb[e]; }

    // stage x for ALL 256 batches: 4 sites x 256 batches float2, coalesced
#pragma unroll
    for (int i = 0; i < 4; i++) {
        const int id = t + 256 * i;
        const int s  = id >> 8;
        const int bb = id & 255;
        xs[id] = ((const float2*)x)[(size_t)(4 * q + s) * 256 + bb];
    }
    __syncthreads();

    // ---- Stage B: R columns into padded smem ----
    {
        const int g  = t >> 4;     // combo e*4+f
        const int jj = t & 15;     // output column
        const int e = g >> 2, f = g & 3;
        const float* P1 = (q < 128) ? SA[e] : SB[f];
        const float* P2 = (q < 128) ? SB[f] : SA[e];

        float acc[16];
#pragma unroll
        for (int k = 0; k < 16; k++) acc[k] = 0.f;
#pragma unroll
        for (int m = 0; m < 16; m++) {
            const float bsc = P2[m * 17 + jj];
#pragma unroll
            for (int k = 0; k < 16; k++)
                acc[k] = fmaf(P1[k * 17 + m], bsc, acc[k]);
        }
        float2* dst = (float2*)&Rsh[g * 288 + jj * 18];
#pragma unroll
        for (int kp = 0; kp < 8; kp++)
            dst[kp] = make_float2(acc[2 * kp], acc[2 * kp + 1]);
    }
    __syncthreads();

    // ---- Stage C: 4 slices of 64 batches, NO barriers ----
    const int bg = t >> 4;      // 16 groups of 4 batches
    const int j  = t & 15;

#pragma unroll 1
    for (int s8 = 0; s8 < 4; s8++) {
        const int b0 = s8 * 64 + bg * 4;

        float cA[4][4], cB[4][4];
#pragma unroll
        for (int bb = 0; bb < 4; bb++) {
            const float2 x0 = xs[0 * 256 + b0 + bb];
            const float2 x1 = xs[1 * 256 + b0 + bb];
            const float2 x2 = xs[2 * 256 + b0 + bb];
            const float2 x3 = xs[3 * 256 + b0 + bb];
            cA[bb][0] = x0.x * x1.x; cA[bb][1] = x0.x * x1.y;
            cA[bb][2] = x0.y * x1.x; cA[bb][3] = x0.y * x1.y;
            cB[bb][0] = x2.x * x3.x; cB[bb][1] = x2.x * x3.y;
            cB[bb][2] = x2.y * x3.x; cB[bb][3] = x2.y * x3.y;
        }

        unsigned long long acc[4][8];
#pragma unroll
        for (int bb = 0; bb < 4; bb++)
#pragma unroll
            for (int kp = 0; kp < 8; kp++) acc[bb][kp] = 0ull;

#pragma unroll
        for (int e = 0; e < 4; e++) {
#pragma unroll
            for (int f = 0; f < 4; f++) {
                const unsigned long long c0 = pack2(cA[0][e] * cB[0][f], cA[0][e] * cB[0][f]);
                const unsigned long long c1 = pack2(cA[1][e] * cB[1][f], cA[1][e] * cB[1][f]);
                const unsigned long long c2 = pack2(cA[2][e] * cB[2][f], cA[2][e] * cB[2][f]);
                const unsigned long long c3 = pack2(cA[3][e] * cB[3][f], cA[3][e] * cB[3][f]);
                const unsigned long long* Rp =
                    (const unsigned long long*)&Rsh[(e * 4 + f) * 288 + j * 18];
#pragma unroll
                for (int kp = 0; kp < 8; kp++) {
                    const unsigned long long rr = Rp[kp];   // conflict-free LDS.64
                    fma2(acc[0][kp], c0, rr);
                    fma2(acc[1][kp], c1, rr);
                    fma2(acc[2][kp], c2, rr);
                    fma2(acc[3][kp], c3, rr);
                }
            }
        }

#pragma unroll
        for (int bb = 0; bb < 4; bb++) {
            unsigned w[8];
#pragma unroll
            for (int kp = 0; kp < 8; kp++) w[kp] = cvt_bf16x2(acc[bb][kp]);
            uint4* dst = (uint4*)(g_Qh + (size_t)(b0 + bb) * 65536 + q * 256 + j * 16);
            dst[0] = make_uint4(w[0], w[1], w[2], w[3]);
            dst[1] = make_uint4(w[4], w[5], w[6], w[7]);
        }
    }
}

// ---------------------------------------------------------------------------
// K2: chains in packed bf16. grid=256 single-warp blocks (one batch each);
// lanes 0-15 left chain (q ascending), lanes 16-31 right chain (q descending,
// transposed quads). Depth-8 register prefetch, compile-time slot indices.
// Per step: 2 LDS.128 (packed v) + 8 HFMA2 + 2 HADD2 + PRMT + STS.16 +
// syncwarp. Q bf16x2 words are used directly as operands (no decode).
// ---------------------------------------------------------------------------
__global__ __launch_bounds__(32)
void chain_kernel(const float* __restrict__ Aout, float* __restrict__ out)
{
    __shared__ uint4 vsmv[2][2][2];   // [pingpong][half][2] = 16 bf16 per half

    const int b    = blockIdx.x;
    const int lane = threadIdx.x;
    const int h    = lane >> 4;
    const int j    = lane & 15;

    // bf16 column base: index b*65536 + q*256 + j*16 + k ; uint4 = 8 bf16
    const uint4* base = (const uint4*)(g_Qh + (size_t)b * 65536 + j * 16);
    const int dir = h ? -32 : 32;

    uint4 buf[8][2];
#pragma unroll
    for (int d = 0; d < 8; d++) {
        const int q = h ? (255 - d) : d;
        buf[d][0] = base[q * 32 + 0];
        buf[d][1] = base[q * 32 + 1];
    }
    const uint4* pf = base + (h ? (255 - 8) * 32 : 8 * 32);

    // v = e0 in pingpong 0 (bf16 1.0 = 0x3F80)
    ((unsigned short*)&vsmv[0][h][0])[j] = (j == 0) ? (unsigned short)0x3F80
                                                    : (unsigned short)0;
    __syncwarp();

    unsigned r2 = 0;
    for (int T = 0; T < 128; T += 8) {
#pragma unroll
        for (int s = 0; s < 8; s++) {
            const int t  = T + s;
            const int pp = t & 1;

            // packed v: 8 bf16x2 words (v0..v15)
            const uint4 va = vsmv[pp][h][0];
            const uint4 vb = vsmv[pp][h][1];

            unsigned accA = hmul2(va.x, buf[s][0].x);
            unsigned accB = hmul2(va.y, buf[s][0].y);
            hfma2(accA, va.z, buf[s][0].z);
            hfma2(accB, va.w, buf[s][0].w);
            hfma2(accA, vb.x, buf[s][1].x);
            hfma2(accB, vb.y, buf[s][1].y);
            hfma2(accA, vb.z, buf[s][1].z);
            hfma2(accB, vb.w, buf[s][1].w);

            // prefetch step t+8 into slot s (compile-time index, stays in regs)
            if (t + 8 < 128) {
                buf[s][0] = pf[0];
                buf[s][1] = pf[1];
                pf += dir;
            }

            const unsigned ssum = hadd2(accA, accB);
            const unsigned sw   = __byte_perm(ssum, ssum, 0x1032);
            r2 = hadd2(ssum, sw);    // vp duplicated in both bf16 halves

            ((unsigned short*)&vsmv[pp ^ 1][h][0])[j] = (unsigned short)r2;
            __syncwarp();
        }
    }

    // final column value (bf16 -> fp32)
    const float f = __uint_as_float(r2 << 16);

    float al[16], ar[16];
#pragma unroll
    for (int k = 0; k < 16; k++)
        al[k] = __shfl_sync(0xffffffffu, f, k);
#pragma unroll
    for (int k = 0; k < 16; k++)
        ar[k] = __shfl_sync(0xffffffffu, f, 16 + k);

    if (lane < C_DIM) {
        const float4* Ao = (const float4*)(Aout + lane * 256);
        float acc = 0.f;
#pragma unroll
        for (int l = 0; l < 16; l++) {
            const float a = al[l];
#pragma unroll
            for (int rq = 0; rq < 4; rq++) {
                const float4 xv = Ao[l * 4 + rq];
                acc = fmaf(a * xv.x, ar[rq * 4 + 0], acc);
                acc = fmaf(a * xv.y, ar[rq * 4 + 1], acc);
                acc = fmaf(a * xv.z, ar[rq * 4 + 2], acc);
                acc = fmaf(a * xv.w, ar[rq * 4 + 3], acc);
            }
        }
        out[b * C_DIM + lane] = acc;
    }
}

// ---------------------------------------------------------------------------
extern "C" void kernel_launch(void* const* d_in, const int* in_sizes, int n_in,
                              void* d_out, int out_size)
{
    const float* x      = (const float*)d_in[0];  // (N, B, d)
    const float* tensor = (const float*)d_in[1];  // (N, D, D, d)
    const float* Aout   = (const float*)d_in[2];  // (C, D, D)
    float* out = (float*)d_out;                   // (B, C)

    prq_kernel<<<NQUAD, 256>>>(tensor, x);
    chain_kernel<<<B_DIM, 32>>>(Aout, out);
}